// round 2
// baseline (speedup 1.0000x reference)
#include <cuda_runtime.h>
#include <cuda_bf16.h>
#include <float.h>

#define N_BINS 15
#define NUM_SEG (1000 * N_BINS)

// Scratch: per-(class,bin) signed accumulation of (conf - acc).
__device__ float g_seg[NUM_SEG];
// 1 if labels buffer is int64, 0 if int32.
__device__ int g_lab64;

// Detect labels dtype: if labels were int64 with values in [0, C), every high
// 32-bit word is 0. If they're int32, the "high words" are other labels and
// are ~never all zero across 512 samples.
__global__ void detect_and_zero_kernel(const int* __restrict__ labels32, int nprobe) {
    __shared__ int nonzero;
    if (threadIdx.x == 0) nonzero = 0;
    __syncthreads();
    for (int i = threadIdx.x; i < nprobe; i += blockDim.x) {
        if (labels32[2 * i + 1] != 0) atomicOr(&nonzero, 1);
    }
    __syncthreads();
    if (threadIdx.x == 0) g_lab64 = nonzero ? 0 : 1;
    // Zero the scratch too (grid is 1 block; NUM_SEG/256 ~ 59 iters)
    for (int i = threadIdx.x; i < NUM_SEG; i += blockDim.x) g_seg[i] = 0.0f;
}

// One warp per row. Online softmax: running (max m, argmax idx, sum s of exp(l - m)).
__global__ __launch_bounds__(256)
void ecce_main_kernel(const float* __restrict__ logits,
                      const void* __restrict__ labels,
                      int N, int C) {
    int warp = (blockIdx.x * blockDim.x + threadIdx.x) >> 5;
    int lane = threadIdx.x & 31;
    if (warp >= N) return;

    const float4* row = reinterpret_cast<const float4*>(logits + (size_t)warp * C);
    const int nvec = C >> 2;  // 250

    float m = -FLT_MAX;
    float s = 0.0f;
    int   idx = 0x7FFFFFFF;

    for (int i = lane; i < nvec; i += 32) {
        float4 v = row[i];
        int base = i << 2;
        #pragma unroll
        for (int k = 0; k < 4; k++) {
            float x = (k == 0) ? v.x : (k == 1) ? v.y : (k == 2) ? v.z : v.w;
            int j = base + k;
            if (x > m) {
                s = s * __expf(m - x) + 1.0f;
                m = x;
                idx = j;
            } else {
                s += __expf(x - m);
            }
        }
    }

    // Warp reduction of (m, idx, s); tie-break toward lower index (first argmax).
    #pragma unroll
    for (int off = 16; off > 0; off >>= 1) {
        float m2 = __shfl_down_sync(0xFFFFFFFFu, m, off);
        float s2 = __shfl_down_sync(0xFFFFFFFFu, s, off);
        int   i2 = __shfl_down_sync(0xFFFFFFFFu, idx, off);
        if (m2 > m || (m2 == m && i2 < idx)) {
            s = s * __expf(m - m2) + s2;
            m = m2;
            idx = i2;
        } else {
            s += s2 * __expf(m2 - m);
        }
    }

    if (lane == 0) {
        float conf = 1.0f / s;  // = exp(0)/sum(exp(l - max))
        int bin = (int)ceilf(conf * (float)N_BINS) - 1;
        bin = min(max(bin, 0), N_BINS - 1);
        int lab;
        if (g_lab64) {
            lab = (int)((const long long*)labels)[warp];
        } else {
            lab = ((const int*)labels)[warp];
        }
        lab = min(max(lab, 0), 999);  // defensive: never index scratch OOB
        float acc = (idx == lab) ? 1.0f : 0.0f;
        atomicAdd(&g_seg[lab * N_BINS + bin], conf - acc);
    }
}

// Single-block reduction: ecce = sum(|seg|) / N
__global__ __launch_bounds__(256)
void ecce_reduce_kernel(float* __restrict__ out, int N) {
    __shared__ float sh[256];
    float acc = 0.0f;
    for (int i = threadIdx.x; i < NUM_SEG; i += 256)
        acc += fabsf(g_seg[i]);
    sh[threadIdx.x] = acc;
    __syncthreads();
    for (int off = 128; off > 0; off >>= 1) {
        if (threadIdx.x < off) sh[threadIdx.x] += sh[threadIdx.x + off];
        __syncthreads();
    }
    if (threadIdx.x == 0) out[0] = sh[0] / (float)N;
}

extern "C" void kernel_launch(void* const* d_in, const int* in_sizes, int n_in,
                              void* d_out, int out_size) {
    // Logits is the (much) larger input; don't assume ordering.
    int i_logits = (in_sizes[0] >= in_sizes[1]) ? 0 : 1;
    int i_labels = 1 - i_logits;

    const float* logits = (const float*)d_in[i_logits];
    const void*  labels = d_in[i_labels];
    float*       out    = (float*)d_out;

    int N = in_sizes[i_labels];           // 131072
    int C = in_sizes[i_logits] / N;       // 1000

    // Probe 512 entries; if labels are int32 this reads 4 KB of a 512 KB
    // buffer, if int64 it reads 4 KB of a 1 MB buffer — safe either way.
    int nprobe = (N >= 1024) ? 512 : (N / 2);
    detect_and_zero_kernel<<<1, 256>>>((const int*)labels, nprobe);

    int warps_per_block = 256 / 32;       // 8 rows per block
    int blocks = (N + warps_per_block - 1) / warps_per_block;
    ecce_main_kernel<<<blocks, 256>>>(logits, labels, N, C);

    ecce_reduce_kernel<<<1, 256>>>(out, N);
}

// round 3
// speedup vs baseline: 1.5794x; 1.5794x over previous
#include <cuda_runtime.h>
#include <cuda_bf16.h>
#include <float.h>

#define N_BINS 15
#define NUM_CLS 1000
#define NUM_SEG (NUM_CLS * N_BINS)

// Scratch: per-(class,bin) signed accumulation of (conf - acc).
__device__ float g_seg[NUM_SEG];
// 1 if labels buffer is int64, 0 if int32.
__device__ int g_lab64;

// Zero scratch across the grid; block 0 warp 0 probes labels dtype.
// If labels are int64 with values in [0,1000), every high 32-bit word is 0.
// If int32, the probed "high words" are other labels: all-zero has prob ~1e-384.
__global__ void prep_kernel(const int* __restrict__ labels32, int nprobe) {
    int tid = blockIdx.x * blockDim.x + threadIdx.x;
    for (int i = tid; i < NUM_SEG; i += gridDim.x * blockDim.x)
        g_seg[i] = 0.0f;
    if (blockIdx.x == 0 && threadIdx.x < 32) {
        int lane = threadIdx.x;
        int nz = 0;
        for (int i = lane; i < nprobe; i += 32)
            nz |= labels32[2 * i + 1];
        unsigned any = __ballot_sync(0xFFFFFFFFu, nz != 0);
        if (lane == 0) g_lab64 = (any == 0) ? 1 : 0;
    }
}

// One warp per row. Front-batched loads (MLP=8/lane), local max+argmax,
// then exp-sum, then warp merge.
__global__ __launch_bounds__(256)
void ecce_main_kernel(const float* __restrict__ logits,
                      const void* __restrict__ labels,
                      int N, int C) {
    int warp = (blockIdx.x * blockDim.x + threadIdx.x) >> 5;
    int lane = threadIdx.x & 31;
    if (warp >= N) return;

    const float4* row = reinterpret_cast<const float4*>(logits + (size_t)warp * C);
    const int nvec = C >> 2;

    float m = -FLT_MAX;
    float s = 0.0f;
    int   idx = 0x7FFFFFFF;

    if (nvec == 250) {
        // ---- specialized C=1000 path ----
        const float4 pad = make_float4(-FLT_MAX, -FLT_MAX, -FLT_MAX, -FLT_MAX);
        float4 v[8];
        // Issue all 8 LDG.128 back-to-back before any consumer.
        #pragma unroll
        for (int k = 0; k < 8; k++) {
            int i = lane + (k << 5);
            v[k] = (i < 250) ? row[i] : pad;
        }
        // Phase A: local max + argmax (first occurrence; per-lane indices increase).
        #pragma unroll
        for (int k = 0; k < 8; k++) {
            int base = (lane + (k << 5)) << 2;
            #pragma unroll
            for (int e = 0; e < 4; e++) {
                float x = (e == 0) ? v[k].x : (e == 1) ? v[k].y : (e == 2) ? v[k].z : v[k].w;
                if (x > m) { m = x; idx = base + e; }
            }
        }
        // Phase B: un-rescaled exp-sum relative to local max (pads give exp(-inf)=0).
        #pragma unroll
        for (int k = 0; k < 8; k++) {
            s += __expf(v[k].x - m) + __expf(v[k].y - m)
               + __expf(v[k].z - m) + __expf(v[k].w - m);
        }
    } else {
        // ---- generic fallback (online softmax) ----
        for (int i = lane; i < nvec; i += 32) {
            float4 v = row[i];
            int base = i << 2;
            #pragma unroll
            for (int e = 0; e < 4; e++) {
                float x = (e == 0) ? v.x : (e == 1) ? v.y : (e == 2) ? v.z : v.w;
                int j = base + e;
                if (x > m) {
                    s = s * __expf(m - x) + 1.0f;
                    m = x; idx = j;
                } else {
                    s += __expf(x - m);
                }
            }
        }
    }

    // Warp merge of (m, idx, s); tie-break toward lower index (first argmax).
    #pragma unroll
    for (int off = 16; off > 0; off >>= 1) {
        float m2 = __shfl_down_sync(0xFFFFFFFFu, m, off);
        float s2 = __shfl_down_sync(0xFFFFFFFFu, s, off);
        int   i2 = __shfl_down_sync(0xFFFFFFFFu, idx, off);
        if (m2 > m || (m2 == m && i2 < idx)) {
            s = s * __expf(m - m2) + s2;
            m = m2; idx = i2;
        } else {
            s += s2 * __expf(m2 - m);
        }
    }

    if (lane == 0) {
        float conf = 1.0f / s;  // = exp(0)/sum(exp(l - max))
        int bin = (int)ceilf(conf * (float)N_BINS) - 1;
        bin = min(max(bin, 0), N_BINS - 1);
        int lab;
        if (g_lab64) lab = (int)((const long long*)labels)[warp];
        else         lab = ((const int*)labels)[warp];
        lab = min(max(lab, 0), NUM_CLS - 1);  // defensive
        float acc = (idx == lab) ? 1.0f : 0.0f;
        atomicAdd(&g_seg[lab * N_BINS + bin], conf - acc);
    }
}

// Single-block reduction: ecce = sum(|seg|) / N. NUM_SEG % 4 == 0.
__global__ __launch_bounds__(512)
void ecce_reduce_kernel(float* __restrict__ out, int N) {
    __shared__ float sh[512];
    const float4* p = reinterpret_cast<const float4*>(g_seg);
    float acc = 0.0f;
    for (int i = threadIdx.x; i < NUM_SEG / 4; i += 512) {
        float4 v = p[i];
        acc += fabsf(v.x) + fabsf(v.y) + fabsf(v.z) + fabsf(v.w);
    }
    sh[threadIdx.x] = acc;
    __syncthreads();
    for (int off = 256; off > 0; off >>= 1) {
        if (threadIdx.x < off) sh[threadIdx.x] += sh[threadIdx.x + off];
        __syncthreads();
    }
    if (threadIdx.x == 0) out[0] = sh[0] / (float)N;
}

extern "C" void kernel_launch(void* const* d_in, const int* in_sizes, int n_in,
                              void* d_out, int out_size) {
    // Logits is the (much) larger input; don't assume ordering.
    int i_logits = (in_sizes[0] >= in_sizes[1]) ? 0 : 1;
    int i_labels = 1 - i_logits;

    const float* logits = (const float*)d_in[i_logits];
    const void*  labels = d_in[i_labels];
    float*       out    = (float*)d_out;

    int N = in_sizes[i_labels];           // 131072
    int C = in_sizes[i_logits] / N;       // 1000

    // Probe 128 entries: reads 1 KB of a >=512 KB buffer — safe either way.
    int nprobe = (N >= 256) ? 128 : (N / 2);
    prep_kernel<<<30, 512>>>((const int*)labels, nprobe);

    int warps_per_block = 256 / 32;       // 8 rows per block
    int blocks = (N + warps_per_block - 1) / warps_per_block;
    ecce_main_kernel<<<blocks, 256>>>(logits, labels, N, C);

    ecce_reduce_kernel<<<1, 512>>>(out, N);
}